// round 5
// baseline (speedup 1.0000x reference)
#include <cuda_runtime.h>

// ---------------- problem constants ----------------
#define BB   8
#define TT   512
#define DD   512
#define UU   1024
#define VV   50257
#define MM   4096            // BB*TT
#define GRID_CTAS 64

// ---------------- device scratch (static; no allocs) ----------------
// All state tensors in [m][u] layout with m = b*TT + t.
__device__ float g_A1[MM * UU];        // X@Wx1 + b1
__device__ float g_H1[MM * UU];
__device__ float g_H2[MM * UU];
__device__ float g_rowsum[MM];

// grid-barrier state (reset every run by init_kernel -> deterministic replays)
__device__ unsigned int g_bar_count;
__device__ volatile unsigned int g_bar_gen;

// ---------------- init: zero rowsum + barrier state ----------------
__global__ void init_kernel() {
    int i = blockIdx.x * 256 + threadIdx.x;
    if (i < MM) g_rowsum[i] = 0.0f;
    if (i == 0) { g_bar_count = 0u; g_bar_gen = 0u; }
}

// ---------------- A1 = X @ Wx1 + b1  (M=4096, K=512, N=1024) ----------------
__global__ void gemm_a1_kernel(const float* __restrict__ X,
                               const float* __restrict__ W,
                               const float* __restrict__ b1) {
    const int K = DD, N = UU;
    __shared__ float As[16][132];
    __shared__ float Bs[16][132];
    int bm = blockIdx.y * 128;
    int bn = blockIdx.x * 128;
    int tid = threadIdx.x;
    int ty = tid >> 4, tx = tid & 15;

    float acc[8][8];
    #pragma unroll
    for (int i = 0; i < 8; i++)
        #pragma unroll
        for (int j = 0; j < 8; j++) acc[i][j] = 0.0f;

    for (int k0 = 0; k0 < K; k0 += 16) {
        #pragma unroll
        for (int l = 0; l < 8; l++) {
            int idx = tid + l * 256;
            int ar = idx >> 4, ak = idx & 15;
            As[ak][ar] = X[(size_t)(bm + ar) * K + k0 + ak];
            int bk = idx >> 7, bc = idx & 127;
            Bs[bk][bc] = W[(size_t)(k0 + bk) * N + bn + bc];
        }
        __syncthreads();
        #pragma unroll
        for (int kk = 0; kk < 16; kk++) {
            float ra[8], rb[8];
            #pragma unroll
            for (int i = 0; i < 8; i++) ra[i] = As[kk][ty * 8 + i];
            #pragma unroll
            for (int j = 0; j < 8; j++) rb[j] = Bs[kk][tx * 8 + j];
            #pragma unroll
            for (int i = 0; i < 8; i++)
                #pragma unroll
                for (int j = 0; j < 8; j++) acc[i][j] = fmaf(ra[i], rb[j], acc[i][j]);
        }
        __syncthreads();
    }

    #pragma unroll
    for (int i = 0; i < 8; i++) {
        int m = bm + ty * 8 + i;
        #pragma unroll
        for (int j = 0; j < 8; j++) {
            int n = bn + tx * 8 + j;
            g_A1[(size_t)m * UU + n] = acc[i][j] + b1[n];
        }
    }
}

// ---------------- grid barrier (sense-reversing, all CTAs co-resident) ----------------
__device__ __forceinline__ void grid_sync(unsigned int target) {
    __threadfence();                 // flush this thread's STGs to GPU scope
    __syncthreads();                 // all CTA threads' fences done
    if (threadIdx.x == 0) {
        unsigned int arrived = atomicAdd(&g_bar_count, 1u) + 1u;
        if (arrived == GRID_CTAS) {
            g_bar_count = 0u;
            __threadfence();
            g_bar_gen = target;      // release
        } else {
            while (g_bar_gen != target) __nanosleep(32);
            __threadfence();         // acquire-ish
        }
    }
    __syncthreads();
}

// ---------------- persistent recurrence: all 512 steps in ONE launch ----------------
// 64 CTAs x 256 threads. Each CTA owns 16 u-columns.
// Thread layout: ul = tid & 15 (u within slice), kc = tid >> 4 (16 k-chunks of 64).
// h vectors staged in smem ([b][k], warp-broadcast reads); W read coalesced from L2.
__global__ void __launch_bounds__(256, 1)
rnn_persistent_kernel(const float* __restrict__ Wh1,
                      const float* __restrict__ Wx2,
                      const float* __restrict__ Wh2,
                      const float* __restrict__ b2) {
    __shared__ float hs[BB * UU];            // 32 KB
    __shared__ float psum[16 * BB * 16];     // 8 KB: [kc][b][ul]
    int tid = threadIdx.x;
    int ul = tid & 15;
    int kc = tid >> 4;
    int u = blockIdx.x * 16 + ul;
    int k0 = kc * 64;
    unsigned int gen = 0;

    for (int t = 0; t < TT; t++) {
        // ================ layer 1: h1[t] = tanh(A1[t] + h1[t-1] @ Wh1) ================
        if (t == 0) {
            for (int i = tid; i < BB * UU; i += 256) hs[i] = 0.0f;
        } else {
            for (int i = tid; i < (BB * UU) / 4; i += 256) {
                int b = i >> 8, o4 = i & 255;
                ((float4*)hs)[i] =
                    *((const float4*)(g_H1 + (size_t)(b * TT + t - 1) * UU) + o4);
            }
        }
        __syncthreads();

        float acc[BB];
        #pragma unroll
        for (int b = 0; b < BB; b++) acc[b] = 0.0f;
        for (int k = k0; k < k0 + 64; k++) {
            float wv = Wh1[(size_t)k * UU + u];
            #pragma unroll
            for (int b = 0; b < BB; b++) acc[b] = fmaf(hs[b * UU + k], wv, acc[b]);
        }
        #pragma unroll
        for (int b = 0; b < BB; b++) psum[(kc * BB + b) * 16 + ul] = acc[b];
        __syncthreads();

        if (tid < 128) {
            int b = tid >> 4, uo = tid & 15;
            float tot = 0.0f;
            #pragma unroll
            for (int kk = 0; kk < 16; kk++) tot += psum[(kk * BB + b) * 16 + uo];
            int uu = blockIdx.x * 16 + uo;
            size_t m = (size_t)(b * TT + t);
            g_H1[m * UU + uu] = tanhf(g_A1[m * UU + uu] + tot);
        }
        gen++;
        grid_sync(gen);   // h1[t] visible to all CTAs

        // ================ layer 2: h2[t] = tanh(h1[t]@Wx2 + h2[t-1]@Wh2 + b2) ================
        for (int i = tid; i < (BB * UU) / 4; i += 256) {
            int b = i >> 8, o4 = i & 255;
            ((float4*)hs)[i] =
                *((const float4*)(g_H1 + (size_t)(b * TT + t) * UU) + o4);
        }
        __syncthreads();
        #pragma unroll
        for (int b = 0; b < BB; b++) acc[b] = 0.0f;
        for (int k = k0; k < k0 + 64; k++) {
            float wv = Wx2[(size_t)k * UU + u];
            #pragma unroll
            for (int b = 0; b < BB; b++) acc[b] = fmaf(hs[b * UU + k], wv, acc[b]);
        }
        __syncthreads();   // all reads of hs done before overwrite

        if (t == 0) {
            for (int i = tid; i < BB * UU; i += 256) hs[i] = 0.0f;
        } else {
            for (int i = tid; i < (BB * UU) / 4; i += 256) {
                int b = i >> 8, o4 = i & 255;
                ((float4*)hs)[i] =
                    *((const float4*)(g_H2 + (size_t)(b * TT + t - 1) * UU) + o4);
            }
        }
        __syncthreads();
        for (int k = k0; k < k0 + 64; k++) {
            float wv = Wh2[(size_t)k * UU + u];
            #pragma unroll
            for (int b = 0; b < BB; b++) acc[b] = fmaf(hs[b * UU + k], wv, acc[b]);
        }
        #pragma unroll
        for (int b = 0; b < BB; b++) psum[(kc * BB + b) * 16 + ul] = acc[b];
        __syncthreads();

        if (tid < 128) {
            int b = tid >> 4, uo = tid & 15;
            float tot = 0.0f;
            #pragma unroll
            for (int kk = 0; kk < 16; kk++) tot += psum[(kk * BB + b) * 16 + uo];
            int uu = blockIdx.x * 16 + uo;
            size_t m = (size_t)(b * TT + t);
            g_H2[m * UU + uu] = tanhf(tot + b2[uu]);
        }
        gen++;
        grid_sync(gen);   // h2[t] visible; safe to proceed to step t+1
    }
}

// ---------------- logits GEMM + exp + row-sum (M=4096, K=1024, N=50257) ----------------
__global__ void gemm_logits_kernel(const float* __restrict__ Wout,
                                   const float* __restrict__ bout,
                                   float* __restrict__ out) {
    const int K = UU;
    __shared__ float As[16][132];
    __shared__ float Bs[16][132];
    int bm = blockIdx.y * 128;
    int bn = blockIdx.x * 128;
    int tid = threadIdx.x;
    int ty = tid >> 4, tx = tid & 15;

    float acc[8][8];
    #pragma unroll
    for (int i = 0; i < 8; i++)
        #pragma unroll
        for (int j = 0; j < 8; j++) acc[i][j] = 0.0f;

    for (int k0 = 0; k0 < K; k0 += 16) {
        #pragma unroll
        for (int l = 0; l < 8; l++) {
            int idx = tid + l * 256;
            int ar = idx >> 4, ak = idx & 15;
            As[ak][ar] = g_H2[(size_t)(bm + ar) * K + k0 + ak];
            int bk = idx >> 7, bc = idx & 127;
            int n = bn + bc;
            Bs[bk][bc] = (n < VV) ? Wout[(size_t)(k0 + bk) * VV + n] : 0.0f;
        }
        __syncthreads();
        #pragma unroll
        for (int kk = 0; kk < 16; kk++) {
            float ra[8], rb[8];
            #pragma unroll
            for (int i = 0; i < 8; i++) ra[i] = As[kk][ty * 8 + i];
            #pragma unroll
            for (int j = 0; j < 8; j++) rb[j] = Bs[kk][tx * 8 + j];
            #pragma unroll
            for (int i = 0; i < 8; i++)
                #pragma unroll
                for (int j = 0; j < 8; j++) acc[i][j] = fmaf(ra[i], rb[j], acc[i][j]);
        }
        __syncthreads();
    }

    float rs[8];
    #pragma unroll
    for (int i = 0; i < 8; i++) rs[i] = 0.0f;
    #pragma unroll
    for (int i = 0; i < 8; i++) {
        int m = bm + ty * 8 + i;
        #pragma unroll
        for (int j = 0; j < 8; j++) {
            int n = bn + tx * 8 + j;
            if (n < VV) {
                float e = expf(acc[i][j] + bout[n]);
                out[(size_t)m * VV + n] = e;
                rs[i] += e;
            }
        }
    }
    __syncthreads();
    float* red = &As[0][0];   // reuse smem as [128][16]
    #pragma unroll
    for (int i = 0; i < 8; i++) red[(ty * 8 + i) * 16 + tx] = rs[i];
    __syncthreads();
    if (tid < 128) {
        float ssum = 0.0f;
        #pragma unroll
        for (int q = 0; q < 16; q++) ssum += red[tid * 16 + q];
        atomicAdd(&g_rowsum[bm + tid], ssum);
    }
}

// ---------------- normalize: out /= rowsum ----------------
__global__ void normalize_kernel(float* __restrict__ out) {
    int m = blockIdx.y;
    float inv = 1.0f / g_rowsum[m];
    size_t ro = (size_t)m * VV;
    int base = blockIdx.x * 1024 + threadIdx.x;
    #pragma unroll
    for (int l = 0; l < 4; l++) {
        int n = base + l * 256;
        if (n < VV) out[ro + n] *= inv;
    }
}

// ---------------- launch (5 graph nodes total) ----------------
extern "C" void kernel_launch(void* const* d_in, const int* in_sizes, int n_in,
                              void* d_out, int out_size) {
    // Signature order: inputs, W_x1, W_h1, b1, W_x2, W_h2, b2, W_out, b_out
    const float* X    = (const float*)d_in[0];
    const float* Wx1  = (const float*)d_in[1];
    const float* Wh1  = (const float*)d_in[2];
    const float* b1   = (const float*)d_in[3];
    const float* Wx2  = (const float*)d_in[4];
    const float* Wh2  = (const float*)d_in[5];
    const float* b2   = (const float*)d_in[6];
    const float* Wout = (const float*)d_in[7];
    const float* bout = (const float*)d_in[8];
    float* out = (float*)d_out;

    init_kernel<<<(MM + 255) / 256, 256>>>();

    gemm_a1_kernel<<<dim3(UU / 128, MM / 128), 256>>>(X, Wx1, b1);

    rnn_persistent_kernel<<<GRID_CTAS, 256>>>(Wh1, Wx2, Wh2, b2);

    gemm_logits_kernel<<<dim3((VV + 127) / 128, MM / 128), 256>>>(Wout, bout, out);

    normalize_kernel<<<dim3((VV + 1023) / 1024, MM), 256>>>(out);
}

// round 6
// speedup vs baseline: 1.2948x; 1.2948x over previous
#include <cuda_runtime.h>

// ---------------- problem constants ----------------
#define BB   8
#define TT   512
#define DD   512
#define UU   1024
#define VV   50257
#define MM   4096            // BB*TT
#define GRID_CTAS 128        // recurrence CTAs (co-resident on 148 SMs)

// ---------------- device scratch (static; no allocs) ----------------
__device__ float g_A1[MM * UU];        // X@Wx1 + b1, [m][u], m = b*TT + t
__device__ float g_H1[MM * UU];
__device__ float g_H2[MM * UU];
__device__ float g_rowsum[MM];

// grid-barrier state (reset every run -> deterministic replays)
__device__ unsigned int g_bar_count;
__device__ volatile unsigned int g_bar_gen;

// ---------------- init ----------------
__global__ void init_kernel() {
    int i = blockIdx.x * 256 + threadIdx.x;
    if (i < MM) g_rowsum[i] = 0.0f;
    if (i == 0) { g_bar_count = 0u; g_bar_gen = 0u; }
}

// ---------------- A1 = X @ Wx1 + b1  (M=4096, K=512, N=1024) ----------------
__global__ void gemm_a1_kernel(const float* __restrict__ X,
                               const float* __restrict__ W,
                               const float* __restrict__ b1) {
    const int K = DD, N = UU;
    __shared__ float As[16][132];
    __shared__ float Bs[16][132];
    int bm = blockIdx.y * 128;
    int bn = blockIdx.x * 128;
    int tid = threadIdx.x;
    int ty = tid >> 4, tx = tid & 15;

    float acc[8][8];
    #pragma unroll
    for (int i = 0; i < 8; i++)
        #pragma unroll
        for (int j = 0; j < 8; j++) acc[i][j] = 0.0f;

    for (int k0 = 0; k0 < K; k0 += 16) {
        #pragma unroll
        for (int l = 0; l < 8; l++) {
            int idx = tid + l * 256;
            int ar = idx >> 4, ak = idx & 15;
            As[ak][ar] = X[(size_t)(bm + ar) * K + k0 + ak];
            int bk = idx >> 7, bc = idx & 127;
            Bs[bk][bc] = W[(size_t)(k0 + bk) * N + bn + bc];
        }
        __syncthreads();
        #pragma unroll
        for (int kk = 0; kk < 16; kk++) {
            float ra[8], rb[8];
            #pragma unroll
            for (int i = 0; i < 8; i++) ra[i] = As[kk][ty * 8 + i];
            #pragma unroll
            for (int j = 0; j < 8; j++) rb[j] = Bs[kk][tx * 8 + j];
            #pragma unroll
            for (int i = 0; i < 8; i++)
                #pragma unroll
                for (int j = 0; j < 8; j++) acc[i][j] = fmaf(ra[i], rb[j], acc[i][j]);
        }
        __syncthreads();
    }

    #pragma unroll
    for (int i = 0; i < 8; i++) {
        int m = bm + ty * 8 + i;
        #pragma unroll
        for (int j = 0; j < 8; j++) {
            int n = bn + tx * 8 + j;
            g_A1[(size_t)m * UU + n] = acc[i][j] + b1[n];
        }
    }
}

// ---------------- grid barrier (sense-reversing) ----------------
__device__ __forceinline__ void grid_sync(unsigned int target) {
    __threadfence();
    __syncthreads();
    if (threadIdx.x == 0) {
        unsigned int arrived = atomicAdd(&g_bar_count, 1u) + 1u;
        if (arrived == GRID_CTAS) {
            g_bar_count = 0u;
            __threadfence();
            g_bar_gen = target;
        } else {
            while (g_bar_gen != target) __nanosleep(32);
            __threadfence();
        }
    }
    __syncthreads();
}

// ---------------- persistent recurrence: all 512 steps in ONE launch ----------------
// 128 CTAs x 256 threads; each CTA owns 8 u-columns.
// ul = tid & 7 (u within slice), kc = tid >> 3 (32 k-chunks of 32).
__global__ void __launch_bounds__(256, 1)
rnn_persistent_kernel(const float* __restrict__ Wh1,
                      const float* __restrict__ Wx2,
                      const float* __restrict__ Wh2,
                      const float* __restrict__ b2) {
    __shared__ float hs[BB * UU];             // 32 KB
    __shared__ float psum[32 * BB * 8];       // 8 KB: [kc][b][ul]
    int tid = threadIdx.x;
    int ul = tid & 7;
    int kc = tid >> 3;
    int u = blockIdx.x * 8 + ul;
    int k0 = kc * 32;
    unsigned int gen = 0;

    for (int t = 0; t < TT; t++) {
        // ======= layer 1: h1[t] = tanh(A1[t] + h1[t-1] @ Wh1) =======
        if (t == 0) {
            for (int i = tid; i < BB * UU; i += 256) hs[i] = 0.0f;
        } else {
            for (int i = tid; i < (BB * UU) / 4; i += 256) {
                int b = i >> 8, o4 = i & 255;
                ((float4*)hs)[i] =
                    *((const float4*)(g_H1 + (size_t)(b * TT + t - 1) * UU) + o4);
            }
        }
        __syncthreads();

        float acc[BB];
        #pragma unroll
        for (int b = 0; b < BB; b++) acc[b] = 0.0f;
        #pragma unroll 4
        for (int k = k0; k < k0 + 32; k++) {
            float wv = Wh1[(size_t)k * UU + u];
            #pragma unroll
            for (int b = 0; b < BB; b++) acc[b] = fmaf(hs[b * UU + k], wv, acc[b]);
        }
        #pragma unroll
        for (int b = 0; b < BB; b++) psum[(kc * BB + b) * 8 + ul] = acc[b];
        __syncthreads();

        if (tid < 64) {
            int b = tid >> 3, uo = tid & 7;
            float tot = 0.0f;
            #pragma unroll
            for (int kk = 0; kk < 32; kk++) tot += psum[(kk * BB + b) * 8 + uo];
            int uu = blockIdx.x * 8 + uo;
            size_t m = (size_t)(b * TT + t);
            g_H1[m * UU + uu] = tanhf(g_A1[m * UU + uu] + tot);
        }
        gen++;
        grid_sync(gen);   // h1[t] visible to all CTAs

        // ======= layer 2: h2[t] = tanh(h1[t]@Wx2 + h2[t-1]@Wh2 + b2) =======
        for (int i = tid; i < (BB * UU) / 4; i += 256) {
            int b = i >> 8, o4 = i & 255;
            ((float4*)hs)[i] =
                *((const float4*)(g_H1 + (size_t)(b * TT + t) * UU) + o4);
        }
        __syncthreads();
        #pragma unroll
        for (int b = 0; b < BB; b++) acc[b] = 0.0f;
        #pragma unroll 4
        for (int k = k0; k < k0 + 32; k++) {
            float wv = Wx2[(size_t)k * UU + u];
            #pragma unroll
            for (int b = 0; b < BB; b++) acc[b] = fmaf(hs[b * UU + k], wv, acc[b]);
        }
        __syncthreads();   // all reads of hs done before overwrite

        if (t == 0) {
            for (int i = tid; i < BB * UU; i += 256) hs[i] = 0.0f;
        } else {
            for (int i = tid; i < (BB * UU) / 4; i += 256) {
                int b = i >> 8, o4 = i & 255;
                ((float4*)hs)[i] =
                    *((const float4*)(g_H2 + (size_t)(b * TT + t - 1) * UU) + o4);
            }
        }
        __syncthreads();
        #pragma unroll 4
        for (int k = k0; k < k0 + 32; k++) {
            float wv = Wh2[(size_t)k * UU + u];
            #pragma unroll
            for (int b = 0; b < BB; b++) acc[b] = fmaf(hs[b * UU + k], wv, acc[b]);
        }
        #pragma unroll
        for (int b = 0; b < BB; b++) psum[(kc * BB + b) * 8 + ul] = acc[b];
        __syncthreads();

        if (tid < 64) {
            int b = tid >> 3, uo = tid & 7;
            float tot = 0.0f;
            #pragma unroll
            for (int kk = 0; kk < 32; kk++) tot += psum[(kk * BB + b) * 8 + uo];
            int uu = blockIdx.x * 8 + uo;
            size_t m = (size_t)(b * TT + t);
            g_H2[m * UU + uu] = tanhf(tot + b2[uu]);
        }
        gen++;
        grid_sync(gen);   // h2[t] visible; proceed to t+1
    }
}

// ---------------- logits GEMM + exp + row-sum (M=4096, K=1024, N=50257) ----------------
// 128x128 tile, BK=16, 256 threads, 8x8/thread, register-staged double buffer,
// 2 CTAs/SM via launch_bounds.
__global__ void __launch_bounds__(256, 2)
gemm_logits_kernel(const float* __restrict__ Wout,
                   const float* __restrict__ bout,
                   float* __restrict__ out) {
    const int K = UU;
    __shared__ float As[16][132];
    __shared__ float Bs[16][132];
    int bm = blockIdx.y * 128;
    int bn = blockIdx.x * 128;
    int tid = threadIdx.x;
    int ty = tid >> 4, tx = tid & 15;

    float acc[8][8];
    #pragma unroll
    for (int i = 0; i < 8; i++)
        #pragma unroll
        for (int j = 0; j < 8; j++) acc[i][j] = 0.0f;

    // ---- preload first k-tile straight into smem ----
    #pragma unroll
    for (int l = 0; l < 8; l++) {
        int idx = tid + l * 256;
        int ar = idx >> 4, ak = idx & 15;
        As[ak][ar] = g_H2[(size_t)(bm + ar) * K + ak];
        int bk = idx >> 7, bc = idx & 127;
        int n = bn + bc;
        Bs[bk][bc] = (n < VV) ? Wout[(size_t)bk * VV + n] : 0.0f;
    }
    __syncthreads();

    for (int k0 = 0; k0 < K; k0 += 16) {
        // ---- prefetch next tile into registers (hides DRAM behind compute) ----
        float pa[8], pb[8];
        if (k0 + 16 < K) {
            #pragma unroll
            for (int l = 0; l < 8; l++) {
                int idx = tid + l * 256;
                int ar = idx >> 4, ak = idx & 15;
                pa[l] = g_H2[(size_t)(bm + ar) * K + k0 + 16 + ak];
                int bk = idx >> 7, bc = idx & 127;
                int n = bn + bc;
                pb[l] = (n < VV) ? Wout[(size_t)(k0 + 16 + bk) * VV + n] : 0.0f;
            }
        }

        // ---- compute current tile ----
        #pragma unroll
        for (int kk = 0; kk < 16; kk++) {
            float ra[8], rb[8];
            #pragma unroll
            for (int i = 0; i < 8; i++) ra[i] = As[kk][ty * 8 + i];
            #pragma unroll
            for (int j = 0; j < 8; j++) rb[j] = Bs[kk][tx * 8 + j];
            #pragma unroll
            for (int i = 0; i < 8; i++)
                #pragma unroll
                for (int j = 0; j < 8; j++) acc[i][j] = fmaf(ra[i], rb[j], acc[i][j]);
        }
        __syncthreads();

        // ---- commit prefetched tile to smem ----
        if (k0 + 16 < K) {
            #pragma unroll
            for (int l = 0; l < 8; l++) {
                int idx = tid + l * 256;
                int ar = idx >> 4, ak = idx & 15;
                As[ak][ar] = pa[l];
                int bk = idx >> 7, bc = idx & 127;
                Bs[bk][bc] = pb[l];
            }
            __syncthreads();
        }
    }

    // ---- epilogue: exp(logit + b_out), write, row-sum ----
    float rs[8];
    #pragma unroll
    for (int i = 0; i < 8; i++) rs[i] = 0.0f;
    #pragma unroll
    for (int i = 0; i < 8; i++) {
        int m = bm + ty * 8 + i;
        #pragma unroll
        for (int j = 0; j < 8; j++) {
            int n = bn + tx * 8 + j;
            if (n < VV) {
                float e = expf(acc[i][j] + bout[n]);
                out[(size_t)m * VV + n] = e;
                rs[i] += e;
            }
        }
    }
    __syncthreads();
    float* red = &As[0][0];   // reuse smem as [128][16]
    #pragma unroll
    for (int i = 0; i < 8; i++) red[(ty * 8 + i) * 16 + tx] = rs[i];
    __syncthreads();
    if (tid < 128) {
        float ssum = 0.0f;
        #pragma unroll
        for (int q = 0; q < 16; q++) ssum += red[tid * 16 + q];
        atomicAdd(&g_rowsum[bm + tid], ssum);
    }
}

// ---------------- normalize: out /= rowsum ----------------
__global__ void normalize_kernel(float* __restrict__ out) {
    int m = blockIdx.y;
    float inv = 1.0f / g_rowsum[m];
    size_t ro = (size_t)m * VV;
    int base = blockIdx.x * 1024 + threadIdx.x;
    #pragma unroll
    for (int l = 0; l < 4; l++) {
        int n = base + l * 256;
        if (n < VV) out[ro + n] *= inv;
    }
}

// ---------------- launch (5 graph nodes) ----------------
extern "C" void kernel_launch(void* const* d_in, const int* in_sizes, int n_in,
                              void* d_out, int out_size) {
    // Signature order: inputs, W_x1, W_h1, b1, W_x2, W_h2, b2, W_out, b_out
    const float* X    = (const float*)d_in[0];
    const float* Wx1  = (const float*)d_in[1];
    const float* Wh1  = (const float*)d_in[2];
    const float* b1   = (const float*)d_in[3];
    const float* Wx2  = (const float*)d_in[4];
    const float* Wh2  = (const float*)d_in[5];
    const float* b2   = (const float*)d_in[6];
    const float* Wout = (const float*)d_in[7];
    const float* bout = (const float*)d_in[8];
    float* out = (float*)d_out;

    init_kernel<<<(MM + 255) / 256, 256>>>();

    gemm_a1_kernel<<<dim3(UU / 128, MM / 128), 256>>>(X, Wx1, b1);

    rnn_persistent_kernel<<<GRID_CTAS, 256>>>(Wh1, Wx2, Wh2, b2);

    gemm_logits_kernel<<<dim3((VV + 127) / 128, MM / 128), 256>>>(Wout, bout, out);

    normalize_kernel<<<dim3((VV + 1023) / 1024, MM), 256>>>(out);
}

// round 9
// speedup vs baseline: 1.9935x; 1.5396x over previous
#include <cuda_runtime.h>
#include <cuda_bf16.h>
#include <stdint.h>

// ---------------- problem constants ----------------
#define BB   8
#define TT   512
#define DD   512
#define UU   1024
#define VV   50257
#define NPAD 50304           // 393 * 128
#define MM   4096            // BB*TT
#define GRID_CTAS 128        // recurrence CTAs

// ---------------- device scratch (static; no allocs) ----------------
__device__ float g_A1[MM * UU];
__device__ float g_H1[MM * UU];
__device__ float g_H2[MM * UU];
__device__ float g_rowsum[MM];
__device__ __nv_bfloat16 g_H2h[MM * UU];            // H2 split hi  [m][k]
__device__ __nv_bfloat16 g_H2l[MM * UU];            // H2 split lo
__device__ __nv_bfloat16 g_WTh[(size_t)NPAD * UU];  // Wout^T hi [n][k]
__device__ __nv_bfloat16 g_WTl[(size_t)NPAD * UU];  // Wout^T lo

__device__ unsigned int g_bar_count;
__device__ volatile unsigned int g_bar_gen;

// ================= helpers =================
__device__ __forceinline__ unsigned smem_u32(const void* p) {
    unsigned a;
    asm("{ .reg .u64 t; cvta.to.shared.u64 t, %1; cvt.u32.u64 %0, t; }"
        : "=r"(a) : "l"(p));
    return a;
}
#define SW128(o) ((o) ^ (((o) >> 3) & 0x70))

__device__ __forceinline__ void ldsm4(uint32_t* r, unsigned addr) {
    asm volatile("ldmatrix.sync.aligned.m8n8.x4.shared.b16 {%0,%1,%2,%3}, [%4];"
                 : "=r"(r[0]), "=r"(r[1]), "=r"(r[2]), "=r"(r[3]) : "r"(addr));
}
__device__ __forceinline__ void mma16816(float* d, const uint32_t* a, const uint32_t* b) {
    asm volatile(
        "mma.sync.aligned.m16n8k16.row.col.f32.bf16.bf16.f32 "
        "{%0,%1,%2,%3}, {%4,%5,%6,%7}, {%8,%9}, {%0,%1,%2,%3};"
        : "+f"(d[0]), "+f"(d[1]), "+f"(d[2]), "+f"(d[3])
        : "r"(a[0]), "r"(a[1]), "r"(a[2]), "r"(a[3]), "r"(b[0]), "r"(b[1]));
}

// ---------------- init ----------------
__global__ void init_kernel() {
    int i = blockIdx.x * 256 + threadIdx.x;
    if (i < MM) g_rowsum[i] = 0.0f;
    if (i == 0) { g_bar_count = 0u; g_bar_gen = 0u; }
}

// ---------------- A1 = X @ Wx1 + b1  (M=4096, K=512, N=1024) ----------------
__global__ void gemm_a1_kernel(const float* __restrict__ X,
                               const float* __restrict__ W,
                               const float* __restrict__ b1) {
    const int K = DD, N = UU;
    __shared__ float As[16][132];
    __shared__ float Bs[16][132];
    int bm = blockIdx.y * 128;
    int bn = blockIdx.x * 128;
    int tid = threadIdx.x;
    int ty = tid >> 4, tx = tid & 15;

    float acc[8][8];
    #pragma unroll
    for (int i = 0; i < 8; i++)
        #pragma unroll
        for (int j = 0; j < 8; j++) acc[i][j] = 0.0f;

    for (int k0 = 0; k0 < K; k0 += 16) {
        #pragma unroll
        for (int l = 0; l < 8; l++) {
            int idx = tid + l * 256;
            int ar = idx >> 4, ak = idx & 15;
            As[ak][ar] = X[(size_t)(bm + ar) * K + k0 + ak];
            int bk = idx >> 7, bc = idx & 127;
            Bs[bk][bc] = W[(size_t)(k0 + bk) * N + bn + bc];
        }
        __syncthreads();
        #pragma unroll
        for (int kk = 0; kk < 16; kk++) {
            float ra[8], rb[8];
            #pragma unroll
            for (int i = 0; i < 8; i++) ra[i] = As[kk][ty * 8 + i];
            #pragma unroll
            for (int j = 0; j < 8; j++) rb[j] = Bs[kk][tx * 8 + j];
            #pragma unroll
            for (int i = 0; i < 8; i++)
                #pragma unroll
                for (int j = 0; j < 8; j++) acc[i][j] = fmaf(ra[i], rb[j], acc[i][j]);
        }
        __syncthreads();
    }

    #pragma unroll
    for (int i = 0; i < 8; i++) {
        int m = bm + ty * 8 + i;
        #pragma unroll
        for (int j = 0; j < 8; j++) {
            int n = bn + tx * 8 + j;
            g_A1[(size_t)m * UU + n] = acc[i][j] + b1[n];
        }
    }
}

// ---------------- grid barrier ----------------
__device__ __forceinline__ void grid_sync(unsigned int target) {
    __threadfence();
    __syncthreads();
    if (threadIdx.x == 0) {
        unsigned int arrived = atomicAdd(&g_bar_count, 1u) + 1u;
        if (arrived == GRID_CTAS) {
            g_bar_count = 0u;
            __threadfence();
            g_bar_gen = target;
        } else {
            while (g_bar_gen != target) __nanosleep(32);
            __threadfence();
        }
    }
    __syncthreads();
}

// ---------------- persistent recurrence (validated R5/R6) ----------------
__global__ void __launch_bounds__(256, 1)
rnn_persistent_kernel(const float* __restrict__ Wh1,
                      const float* __restrict__ Wx2,
                      const float* __restrict__ Wh2,
                      const float* __restrict__ b2) {
    __shared__ float hs[BB * UU];
    __shared__ float psum[32 * BB * 8];
    int tid = threadIdx.x;
    int ul = tid & 7;
    int kc = tid >> 3;
    int u = blockIdx.x * 8 + ul;
    int k0 = kc * 32;
    unsigned int gen = 0;

    for (int t = 0; t < TT; t++) {
        if (t == 0) {
            for (int i = tid; i < BB * UU; i += 256) hs[i] = 0.0f;
        } else {
            for (int i = tid; i < (BB * UU) / 4; i += 256) {
                int b = i >> 8, o4 = i & 255;
                ((float4*)hs)[i] =
                    *((const float4*)(g_H1 + (size_t)(b * TT + t - 1) * UU) + o4);
            }
        }
        __syncthreads();

        float acc[BB];
        #pragma unroll
        for (int b = 0; b < BB; b++) acc[b] = 0.0f;
        #pragma unroll 4
        for (int k = k0; k < k0 + 32; k++) {
            float wv = Wh1[(size_t)k * UU + u];
            #pragma unroll
            for (int b = 0; b < BB; b++) acc[b] = fmaf(hs[b * UU + k], wv, acc[b]);
        }
        #pragma unroll
        for (int b = 0; b < BB; b++) psum[(kc * BB + b) * 8 + ul] = acc[b];
        __syncthreads();

        if (tid < 64) {
            int b = tid >> 3, uo = tid & 7;
            float tot = 0.0f;
            #pragma unroll
            for (int kk = 0; kk < 32; kk++) tot += psum[(kk * BB + b) * 8 + uo];
            int uu = blockIdx.x * 8 + uo;
            size_t m = (size_t)(b * TT + t);
            g_H1[m * UU + uu] = tanhf(g_A1[m * UU + uu] + tot);
        }
        gen++;
        grid_sync(gen);

        for (int i = tid; i < (BB * UU) / 4; i += 256) {
            int b = i >> 8, o4 = i & 255;
            ((float4*)hs)[i] =
                *((const float4*)(g_H1 + (size_t)(b * TT + t) * UU) + o4);
        }
        __syncthreads();
        #pragma unroll
        for (int b = 0; b < BB; b++) acc[b] = 0.0f;
        #pragma unroll 4
        for (int k = k0; k < k0 + 32; k++) {
            float wv = Wx2[(size_t)k * UU + u];
            #pragma unroll
            for (int b = 0; b < BB; b++) acc[b] = fmaf(hs[b * UU + k], wv, acc[b]);
        }
        __syncthreads();

        if (t == 0) {
            for (int i = tid; i < BB * UU; i += 256) hs[i] = 0.0f;
        } else {
            for (int i = tid; i < (BB * UU) / 4; i += 256) {
                int b = i >> 8, o4 = i & 255;
                ((float4*)hs)[i] =
                    *((const float4*)(g_H2 + (size_t)(b * TT + t - 1) * UU) + o4);
            }
        }
        __syncthreads();
        #pragma unroll 4
        for (int k = k0; k < k0 + 32; k++) {
            float wv = Wh2[(size_t)k * UU + u];
            #pragma unroll
            for (int b = 0; b < BB; b++) acc[b] = fmaf(hs[b * UU + k], wv, acc[b]);
        }
        #pragma unroll
        for (int b = 0; b < BB; b++) psum[(kc * BB + b) * 8 + ul] = acc[b];
        __syncthreads();

        if (tid < 64) {
            int b = tid >> 3, uo = tid & 7;
            float tot = 0.0f;
            #pragma unroll
            for (int kk = 0; kk < 32; kk++) tot += psum[(kk * BB + b) * 8 + uo];
            int uu = blockIdx.x * 8 + uo;
            size_t m = (size_t)(b * TT + t);
            g_H2[m * UU + uu] = tanhf(tot + b2[uu]);
        }
        gen++;
        grid_sync(gen);
    }
}

// ---------------- split H2 -> bf16 hi/lo ----------------
__global__ void convert_h2_kernel() {
    int i = blockIdx.x * 256 + threadIdx.x;
    float v = g_H2[i];
    __nv_bfloat16 h = __float2bfloat16(v);
    g_H2h[i] = h;
    g_H2l[i] = __float2bfloat16(v - __bfloat162float(h));
}

// ---------------- transpose + split Wout -> WT hi/lo [n][k] ----------------
__global__ void convert_wout_kernel(const float* __restrict__ Wout) {
    __shared__ float tile[32][33];
    int nb = blockIdx.x * 32, kb = blockIdx.y * 32;
    int tx = threadIdx.x, ty = threadIdx.y;    // (32, 8)
    #pragma unroll
    for (int i = 0; i < 32; i += 8) {
        int k = kb + ty + i, n = nb + tx;
        tile[ty + i][tx] = (n < VV) ? Wout[(size_t)k * VV + n] : 0.0f;
    }
    __syncthreads();
    #pragma unroll
    for (int i = 0; i < 32; i += 8) {
        int n = nb + ty + i, k = kb + tx;
        float v = tile[tx][ty + i];
        __nv_bfloat16 h = __float2bfloat16(v);
        g_WTh[(size_t)n * UU + k] = h;
        g_WTl[(size_t)n * UU + k] = __float2bfloat16(v - __bfloat162float(h));
    }
}

// ---------------- logits GEMM via mma.sync bf16 split (D = H2 @ Wout) ----------------
// CTA tile 128(m) x 128(n); warps 2(m) x 4(n) -> 64x32 per warp; K chunks of 64.
// Smem: 4 SW128-swizzled tiles of 128 rows x 64 bf16 (16KB each) = 64KB dynamic.
#define KC        64
#define NCHUNK    (UU / KC)           // 16
#define SM_AH     0
#define SM_AL     16384
#define SM_BH     32768
#define SM_BL     49152
#define SM_TC_TOT 65536

__global__ void __launch_bounds__(256, 1)
gemm_logits_tc_kernel(const float* __restrict__ bout, float* __restrict__ out) {
    extern __shared__ char smem[];
    unsigned sb = smem_u32(smem);
    int tid = threadIdx.x;
    int wid = tid >> 5, lane = tid & 31;
    int wm = wid >> 2;                // 0..1  (m half)
    int wn = wid & 3;                 // 0..3  (n quarter)
    int bm = blockIdx.x * 128;
    int bn = blockIdx.y * 128;

    float acc[4][4][4];
    #pragma unroll
    for (int i = 0; i < 4; i++)
        #pragma unroll
        for (int j = 0; j < 4; j++)
            #pragma unroll
            for (int q = 0; q < 4; q++) acc[i][j][q] = 0.0f;

    // precomputed ldmatrix lane-address components
    int a_row = (lane & 15);                    // + frag row base
    int a_half = (lane >> 4) * 16;              // byte offset of k-half
    int b_g = lane >> 3;
    int b_row = ((b_g >> 1) * 8) + (lane & 7);  // + frag n base
    int b_half = (b_g & 1) * 16;

    for (int c = 0; c < NCHUNK; c++) {
        int k0 = c * KC;
        // ---- stage chunk: 4 tiles of 128 rows x 64 bf16, SW128 swizzled ----
        #pragma unroll
        for (int q = 0; q < 4; q++) {
            int idx = tid + q * 256;          // 0..1023
            int r = idx >> 3, s = idx & 7;    // row, 16B segment
            unsigned so = SW128(r * 128 + s * 16);
            size_t ga = (size_t)(bm + r) * UU + k0 + s * 8;
            size_t gb = (size_t)(bn + r) * UU + k0 + s * 8;
            *(uint4*)(smem + SM_AH + so) = *(const uint4*)(g_H2h + ga);
            *(uint4*)(smem + SM_AL + so) = *(const uint4*)(g_H2l + ga);
            *(uint4*)(smem + SM_BH + so) = *(const uint4*)(g_WTh + gb);
            *(uint4*)(smem + SM_BL + so) = *(const uint4*)(g_WTl + gb);
        }
        __syncthreads();

        // ---- compute: 4 k16 steps x (AhBh + AhBl + AlBh) ----
        #pragma unroll
        for (int kk = 0; kk < 4; kk++) {
            uint32_t ah[4][4], al[4][4], bh[4][2], bl[4][2];
            #pragma unroll
            for (int mf = 0; mf < 4; mf++) {
                int r = wm * 64 + mf * 16 + a_row;
                unsigned so = SW128(r * 128 + kk * 32 + a_half);
                ldsm4(ah[mf], sb + SM_AH + so);
                ldsm4(al[mf], sb + SM_AL + so);
            }
            #pragma unroll
            for (int nh = 0; nh < 2; nh++) {
                int r = wn * 32 + nh * 16 + b_row;
                unsigned so = SW128(r * 128 + kk * 32 + b_half);
                uint32_t tb[4];
                ldsm4(tb, sb + SM_BH + so);
                bh[nh * 2][0] = tb[0]; bh[nh * 2][1] = tb[1];
                bh[nh * 2 + 1][0] = tb[2]; bh[nh * 2 + 1][1] = tb[3];
                ldsm4(tb, sb + SM_BL + so);
                bl[nh * 2][0] = tb[0]; bl[nh * 2][1] = tb[1];
                bl[nh * 2 + 1][0] = tb[2]; bl[nh * 2 + 1][1] = tb[3];
            }
            #pragma unroll
            for (int mf = 0; mf < 4; mf++)
                #pragma unroll
                for (int nf = 0; nf < 4; nf++) {
                    mma16816(acc[mf][nf], ah[mf], bh[nf]);
                    mma16816(acc[mf][nf], ah[mf], bl[nf]);
                    mma16816(acc[mf][nf], al[mf], bh[nf]);
                }
        }
        __syncthreads();
    }

    // ---- epilogue: exp(logit + bias), write, rowsum via smem ----
    float* srow = (float*)smem;       // 128 floats, smem reused after sync
    if (tid < 128) srow[tid] = 0.0f;
    __syncthreads();

    int mrow = bm + wm * 64;
    int ncol = bn + wn * 32 + (lane & 3) * 2;
    #pragma unroll
    for (int mf = 0; mf < 4; mf++) {
        int r0 = mrow + mf * 16 + (lane >> 2);    // rows r0 and r0+8
        float s0 = 0.0f, s1 = 0.0f;
        size_t ro0 = (size_t)r0 * VV;
        size_t ro1 = (size_t)(r0 + 8) * VV;
        #pragma unroll
        for (int nf = 0; nf < 4; nf++) {
            int n0 = ncol + nf * 8;
            if (n0 < VV) {
                float e = __expf(acc[mf][nf][0] + bout[n0]);
                out[ro0 + n0] = e;  s0 += e;
                e = __expf(acc[mf][nf][2] + bout[n0]);
                out[ro1 + n0] = e;  s1 += e;
            }
            if (n0 + 1 < VV) {
                float e = __expf(acc[mf][nf][1] + bout[n0 + 1]);
                out[ro0 + n0 + 1] = e;  s0 += e;
                e = __expf(acc[mf][nf][3] + bout[n0 + 1]);
                out[ro1 + n0 + 1] = e;  s1 += e;
            }
        }
        atomicAdd(&srow[r0 - bm], s0);
        atomicAdd(&srow[r0 + 8 - bm], s1);
    }
    __syncthreads();
    if (tid < 128) {
        float v = srow[tid];
        if (v != 0.0f) atomicAdd(&g_rowsum[bm + tid], v);
    }
}

// ---------------- normalize: out /= rowsum ----------------
__global__ void normalize_kernel(float* __restrict__ out) {
    int m = blockIdx.y;
    float inv = 1.0f / g_rowsum[m];
    size_t ro = (size_t)m * VV;
    int base = blockIdx.x * 1024 + threadIdx.x;
    #pragma unroll
    for (int l = 0; l < 4; l++) {
        int n = base + l * 256;
        if (n < VV) out[ro + n] *= inv;
    }
}

// ---------------- launch ----------------
extern "C" void kernel_launch(void* const* d_in, const int* in_sizes, int n_in,
                              void* d_out, int out_size) {
    // Signature order: inputs, W_x1, W_h1, b1, W_x2, W_h2, b2, W_out, b_out
    const float* X    = (const float*)d_in[0];
    const float* Wx1  = (const float*)d_in[1];
    const float* Wh1  = (const float*)d_in[2];
    const float* b1   = (const float*)d_in[3];
    const float* Wx2  = (const float*)d_in[4];
    const float* Wh2  = (const float*)d_in[5];
    const float* b2   = (const float*)d_in[6];
    const float* Wout = (const float*)d_in[7];
    const float* bout = (const float*)d_in[8];
    float* out = (float*)d_out;

    // deterministic, not stream work; safe under graph capture
    cudaFuncSetAttribute(gemm_logits_tc_kernel,
                         cudaFuncAttributeMaxDynamicSharedMemorySize, SM_TC_TOT);

    init_kernel<<<(MM + 255) / 256, 256>>>();

    gemm_a1_kernel<<<dim3(UU / 128, MM / 128), 256>>>(X, Wx1, b1);

    rnn_persistent_kernel<<<GRID_CTAS, 256>>>(Wh1, Wx2, Wh2, b2);

    convert_h2_kernel<<<(MM * UU) / 256, 256>>>();
    convert_wout_kernel<<<dim3(NPAD / 32, UU / 32), dim3(32, 8)>>>(Wout);

    gemm_logits_tc_kernel<<<dim3(MM / 128, NPAD / 128), 256, SM_TC_TOT>>>(bout, out);

    normalize_kernel<<<dim3((VV + 1023) / 1024, MM), 256>>>(out);
}